// round 9
// baseline (speedup 1.0000x reference)
#include <cuda_runtime.h>
#include <cuda_bf16.h>
#include <cstdint>

#define NN 50000
#define EE 800000
#define NWT 50000   // EE / 16 edges per warp-tile

// Scratch (device globals; no allocation allowed)
__device__ float g_preS[NN * 128];  // sender-side layer0 precompute (+b0)
__device__ float g_preR[NN * 128];  // receiver-side layer0 precompute
__device__ float g_agg[NN * 64];    // segment-sum accumulator

// ---------------------------------------------------------------------------
__device__ __forceinline__ float relu(float x) { return fmaxf(x, 0.f); }

__device__ __forceinline__ void pf_l1(const void* p) {
    asm volatile("prefetch.global.L1 [%0];" :: "l"(p));
}
__device__ __forceinline__ void pf_l2(const void* p) {
    asm volatile("prefetch.global.L2 [%0];" :: "l"(p));
}

// bf16 hi/lo split of a float pair -> packed bf16x2 (low half = first elem)
__device__ __forceinline__ void split2(float x, float y, uint32_t& hi, uint32_t& lo) {
    __nv_bfloat162 h = __floats2bfloat162_rn(x, y);
    float hx = __bfloat162float(h.x);
    float hy = __bfloat162float(h.y);
    __nv_bfloat162 l = __floats2bfloat162_rn(x - hx, y - hy);
    hi = *reinterpret_cast<uint32_t*>(&h);
    lo = *reinterpret_cast<uint32_t*>(&l);
}

__device__ __forceinline__ void mma_bf16(float (&c)[4],
                                         uint32_t a0, uint32_t a1, uint32_t a2, uint32_t a3,
                                         uint32_t b0, uint32_t b1) {
    asm volatile(
        "mma.sync.aligned.m16n8k16.row.col.f32.bf16.bf16.f32 "
        "{%0,%1,%2,%3}, {%4,%5,%6,%7}, {%8,%9}, {%0,%1,%2,%3};"
        : "+f"(c[0]), "+f"(c[1]), "+f"(c[2]), "+f"(c[3])
        : "r"(a0), "r"(a1), "r"(a2), "r"(a3), "r"(b0), "r"(b1));
}

// Pack one B fragment (n8k16, col layout) for reading lane l of frag f.
__device__ __forceinline__ void pack_frag(const float* __restrict__ W, int ld,
                                          int k0, int n, uint2* hi, uint2* lo, int idx) {
    float w00 = W[(size_t)k0 * ld + n];
    float w01 = W[(size_t)(k0 + 1) * ld + n];
    float w10 = W[(size_t)(k0 + 8) * ld + n];
    float w11 = W[(size_t)(k0 + 9) * ld + n];
    uint32_t h0, l0, h1, l1;
    split2(w00, w01, h0, l0);
    split2(w10, w11, h1, l1);
    hi[idx] = make_uint2(h0, h1);
    lo[idx] = make_uint2(l0, l1);
}

// smem layout (uint2 units): W0H[2048] W0L[2048] W1H[4096] W1L[4096] W2H[2048] W2L[2048]
// then floats: b1[128] b2[64]
#define EDGE_SMEM (16384 * 8 + 768)   // 131840 B

// ---------------------------------------------------------------------------
__global__ void zero_agg_kernel() {
    int i = blockIdx.x * blockDim.x + threadIdx.x;
    if (i < NN * 64) g_agg[i] = 0.0f;
}

// ---------------------------------------------------------------------------
// Per-node precompute (fp32): preS = h_s@W0[0:64] + h_d@W0[128:192] + b0
//                             preR = h_s@W0[64:128] + h_d@W0[192:256]
__global__ __launch_bounds__(512) void node_pre_kernel(
    const float* __restrict__ h_s, const float* __restrict__ h_d,
    const float* __restrict__ W0, const float* __restrict__ b0)
{
    extern __shared__ float sm[];
    float* ws = sm;
    float* nd = sm + 32768;

    int tid = threadIdx.x;
    for (int i = tid; i < 8192; i += 512)
        ((float4*)ws)[i] = ((const float4*)W0)[i];

    int base = blockIdx.x * 64;
    for (int i = tid; i < 2048; i += 512) {
        int r = i >> 5, q = i & 31;
        int n = base + r;
        float4 v = make_float4(0.f, 0.f, 0.f, 0.f);
        if (n < NN) {
            if (q < 16) v = ((const float4*)(h_s + (size_t)n * 64))[q];
            else        v = ((const float4*)(h_d + (size_t)n * 64))[q - 16];
        }
        *((float4*)(nd + r * 132 + q * 4)) = v;
    }
    __syncthreads();

    int ty = tid >> 4, tx = tid & 15;
    int c = tx * 8;
    int r0 = ty * 2;
    float accS[2][8], accR[2][8];
    #pragma unroll
    for (int i = 0; i < 2; i++)
        #pragma unroll
        for (int j = 0; j < 8; j++) { accS[i][j] = 0.f; accR[i][j] = 0.f; }

    #pragma unroll 4
    for (int k = 0; k < 64; k++) {
        float a0 = nd[r0 * 132 + k];
        float a1 = nd[r0 * 132 + 132 + k];
        float e0 = nd[r0 * 132 + 64 + k];
        float e1 = nd[r0 * 132 + 132 + 64 + k];
        float wsa[8], wra[8], wsb[8], wrb[8];
        *(float4*)&wsa[0] = *(float4*)(ws + k * 128 + c);
        *(float4*)&wsa[4] = *(float4*)(ws + k * 128 + c + 4);
        *(float4*)&wra[0] = *(float4*)(ws + (64 + k) * 128 + c);
        *(float4*)&wra[4] = *(float4*)(ws + (64 + k) * 128 + c + 4);
        *(float4*)&wsb[0] = *(float4*)(ws + (128 + k) * 128 + c);
        *(float4*)&wsb[4] = *(float4*)(ws + (128 + k) * 128 + c + 4);
        *(float4*)&wrb[0] = *(float4*)(ws + (192 + k) * 128 + c);
        *(float4*)&wrb[4] = *(float4*)(ws + (192 + k) * 128 + c + 4);
        #pragma unroll
        for (int j = 0; j < 8; j++) {
            accS[0][j] += a0 * wsa[j] + e0 * wsb[j];
            accS[1][j] += a1 * wsa[j] + e1 * wsb[j];
            accR[0][j] += a0 * wra[j] + e0 * wrb[j];
            accR[1][j] += a1 * wra[j] + e1 * wrb[j];
        }
    }

    float bv[8];
    *(float4*)&bv[0] = *(const float4*)(b0 + c);
    *(float4*)&bv[4] = *(const float4*)(b0 + c + 4);
    #pragma unroll
    for (int i = 0; i < 2; i++) {
        int n = base + r0 + i;
        if (n < NN) {
            #pragma unroll
            for (int j = 0; j < 8; j++) {
                g_preS[(size_t)n * 128 + c + j] = accS[i][j] + bv[j];
                g_preR[(size_t)n * 128 + c + j] = accR[i][j];
            }
        }
    }
}

// ---------------------------------------------------------------------------
// Warp-autonomous HMMA edge kernel with next-tile software prefetch.
__global__ __launch_bounds__(256, 1) void edge_kernel(
    const float* __restrict__ edge_feat,
    const int* __restrict__ sender, const int* __restrict__ receiver,
    const float* __restrict__ h_d,
    const float* __restrict__ W0, const float* __restrict__ W1,
    const float* __restrict__ b1, const float* __restrict__ W2,
    const float* __restrict__ b2)
{
    extern __shared__ unsigned char smraw[];
    uint2* W0H = (uint2*)smraw;        // 2048
    uint2* W0L = W0H + 2048;
    uint2* W1H = W0L + 2048;           // 4096
    uint2* W1L = W1H + 4096;
    uint2* W2H = W1L + 4096;           // 2048
    uint2* W2L = W2H + 2048;
    float* b1s = (float*)(W2L + 2048); // 128
    float* b2s = b1s + 128;            // 64

    int tid = threadIdx.x, wid = tid >> 5, lane = tid & 31;
    int q = lane & 3, g = lane >> 2;

    // ---- one-time fragment prepack ----
    for (int i = tid; i < 2048; i += 256) {          // W0e: 64 frags
        int f = i >> 5, l = i & 31;
        int s = f >> 4, j = f & 15;
        pack_frag(W0 + 256 * 128, 128, 16 * s + (l & 3) * 2, 8 * j + (l >> 2), W0H, W0L, i);
    }
    for (int i = tid; i < 4096; i += 256) {          // W1: 128 frags
        int f = i >> 5, l = i & 31;
        int s = f >> 4, j = f & 15;
        pack_frag(W1, 128, 16 * s + (l & 3) * 2, 8 * j + (l >> 2), W1H, W1L, i);
    }
    for (int i = tid; i < 2048; i += 256) {          // W2: 64 frags
        int f = i >> 5, l = i & 31;
        int s = f >> 3, j = f & 7;
        pack_frag(W2, 64, 16 * s + (l & 3) * 2, 8 * j + (l >> 2), W2H, W2L, i);
    }
    if (tid < 128) b1s[tid] = b1[tid];
    if (tid < 64)  b2s[tid] = b2[tid];
    __syncthreads();

    int stride = gridDim.x * 8;
    int wt = blockIdx.x * 8 + wid;

    // current tile indices carried in registers
    int cs0 = 0, cs1 = 0, cr0 = 0, cr1 = 0;
    if (wt < NWT) {
        int eb = wt * 16;
        cs0 = sender[eb + g];     cs1 = sender[eb + 8 + g];
        cr0 = receiver[eb + g];   cr1 = receiver[eb + 8 + g];
    }

    for (; wt < NWT; wt += stride) {
        int ebase = wt * 16;
        int r0 = ebase + g, r1 = r0 + 8;
        int s0 = cs0, s1 = cs1, rc0 = cr0, rc1 = cr1;

        // ---- prefetch next tile (indices kept for next iteration) ----
        int nt = wt + stride;
        if (nt < NWT) {
            int nb = nt * 16;
            int ns0 = sender[nb + g],   ns1 = sender[nb + 8 + g];
            int nr0 = receiver[nb + g], nr1 = receiver[nb + 8 + g];
            // preS/preR rows (512 B each): 4 lanes x 128 B -> L2 (DRAM-hide)
            pf_l2(g_preS + (size_t)ns0 * 128 + q * 32);
            pf_l2(g_preS + (size_t)ns1 * 128 + q * 32);
            pf_l2(g_preR + (size_t)nr0 * 128 + q * 32);
            pf_l2(g_preR + (size_t)nr1 * 128 + q * 32);
            if (q < 2) {
                // edge_feat rows (256 B) + h_d rows (256 B) -> L1
                pf_l1(edge_feat + (size_t)(nb + g) * 64 + q * 32);
                pf_l1(edge_feat + (size_t)(nb + 8 + g) * 64 + q * 32);
                pf_l1(h_d + (size_t)ns0 * 64 + q * 32);
                pf_l1(h_d + (size_t)ns1 * 64 + q * 32);
                pf_l1(h_d + (size_t)nr0 * 64 + q * 32);
                pf_l1(h_d + (size_t)nr1 * 64 + q * 32);
            }
            cs0 = ns0; cs1 = ns1; cr0 = nr0; cr1 = nr1;
        }

        // ---- layer 0 C init: preS[s] + preR[rc]  (b0 folded in preS) ----
        float c0[16][4];
        {
            const float* pS0 = g_preS + (size_t)s0 * 128 + 2 * q;
            const float* pS1 = g_preS + (size_t)s1 * 128 + 2 * q;
            const float* pR0 = g_preR + (size_t)rc0 * 128 + 2 * q;
            const float* pR1 = g_preR + (size_t)rc1 * 128 + 2 * q;
            #pragma unroll
            for (int j = 0; j < 16; j++) {
                float2 a = *(const float2*)(pS0 + 8 * j);
                float2 b = *(const float2*)(pR0 + 8 * j);
                float2 e = *(const float2*)(pS1 + 8 * j);
                float2 d = *(const float2*)(pR1 + 8 * j);
                c0[j][0] = a.x + b.x; c0[j][1] = a.y + b.y;
                c0[j][2] = e.x + d.x; c0[j][3] = e.y + d.y;
            }
        }

        // ---- layer 0 mma: C += ef[16,64] @ W0e[64,128] ----
        {
            const float* e0p = edge_feat + (size_t)r0 * 64 + 2 * q;
            const float* e1p = edge_feat + (size_t)r1 * 64 + 2 * q;
            #pragma unroll
            for (int s = 0; s < 4; s++) {
                float2 ea = *(const float2*)(e0p + 16 * s);
                float2 eb = *(const float2*)(e0p + 16 * s + 8);
                float2 ec = *(const float2*)(e1p + 16 * s);
                float2 ed = *(const float2*)(e1p + 16 * s + 8);
                uint32_t ah[4], al[4];
                split2(ea.x, ea.y, ah[0], al[0]);
                split2(ec.x, ec.y, ah[1], al[1]);
                split2(eb.x, eb.y, ah[2], al[2]);
                split2(ed.x, ed.y, ah[3], al[3]);
                #pragma unroll
                for (int j = 0; j < 16; j++) {
                    uint2 bh = W0H[(s * 16 + j) * 32 + lane];
                    uint2 bl = W0L[(s * 16 + j) * 32 + lane];
                    mma_bf16(c0[j], ah[0], ah[1], ah[2], ah[3], bh.x, bh.y);
                    mma_bf16(c0[j], ah[0], ah[1], ah[2], ah[3], bl.x, bl.y);
                    mma_bf16(c0[j], al[0], al[1], al[2], al[3], bh.x, bh.y);
                }
            }
        }

        // ---- layer 1: C1 = relu(C0) @ W1 + b1 ----
        float c1[16][4];
        #pragma unroll
        for (int j = 0; j < 16; j++) {
            float2 bb = *(const float2*)(b1s + 8 * j + 2 * q);
            c1[j][0] = bb.x; c1[j][1] = bb.y; c1[j][2] = bb.x; c1[j][3] = bb.y;
        }
        #pragma unroll
        for (int s = 0; s < 8; s++) {
            uint32_t ah[4], al[4];
            split2(relu(c0[2 * s][0]),     relu(c0[2 * s][1]),     ah[0], al[0]);
            split2(relu(c0[2 * s][2]),     relu(c0[2 * s][3]),     ah[1], al[1]);
            split2(relu(c0[2 * s + 1][0]), relu(c0[2 * s + 1][1]), ah[2], al[2]);
            split2(relu(c0[2 * s + 1][2]), relu(c0[2 * s + 1][3]), ah[3], al[3]);
            #pragma unroll
            for (int j = 0; j < 16; j++) {
                uint2 bh = W1H[(s * 16 + j) * 32 + lane];
                uint2 bl = W1L[(s * 16 + j) * 32 + lane];
                mma_bf16(c1[j], ah[0], ah[1], ah[2], ah[3], bh.x, bh.y);
                mma_bf16(c1[j], ah[0], ah[1], ah[2], ah[3], bl.x, bl.y);
                mma_bf16(c1[j], al[0], al[1], al[2], al[3], bh.x, bh.y);
            }
        }

        // ---- layer 2: C2 = relu(C1) @ W2 + b2 ----
        float c2[8][4];
        #pragma unroll
        for (int j = 0; j < 8; j++) {
            float2 bb = *(const float2*)(b2s + 8 * j + 2 * q);
            c2[j][0] = bb.x; c2[j][1] = bb.y; c2[j][2] = bb.x; c2[j][3] = bb.y;
        }
        #pragma unroll
        for (int s = 0; s < 8; s++) {
            uint32_t ah[4], al[4];
            split2(relu(c1[2 * s][0]),     relu(c1[2 * s][1]),     ah[0], al[0]);
            split2(relu(c1[2 * s][2]),     relu(c1[2 * s][3]),     ah[1], al[1]);
            split2(relu(c1[2 * s + 1][0]), relu(c1[2 * s + 1][1]), ah[2], al[2]);
            split2(relu(c1[2 * s + 1][2]), relu(c1[2 * s + 1][3]), ah[3], al[3]);
            #pragma unroll
            for (int j = 0; j < 8; j++) {
                uint2 bh = W2H[(s * 8 + j) * 32 + lane];
                uint2 bl = W2L[(s * 8 + j) * 32 + lane];
                mma_bf16(c2[j], ah[0], ah[1], ah[2], ah[3], bh.x, bh.y);
                mma_bf16(c2[j], ah[0], ah[1], ah[2], ah[3], bl.x, bl.y);
                mma_bf16(c2[j], al[0], al[1], al[2], al[3], bh.x, bh.y);
            }
        }

        // ---- epilogue: psi = relu(C2); scatter psi * (h_dj - h_di) ----
        {
            const float* hs0 = h_d + (size_t)s0 * 64 + 2 * q;
            const float* hr0 = h_d + (size_t)rc0 * 64 + 2 * q;
            const float* hs1 = h_d + (size_t)s1 * 64 + 2 * q;
            const float* hr1 = h_d + (size_t)rc1 * 64 + 2 * q;
            float* ag0 = g_agg + (size_t)rc0 * 64 + 2 * q;
            float* ag1 = g_agg + (size_t)rc1 * 64 + 2 * q;
            #pragma unroll
            for (int j = 0; j < 8; j++) {
                float p00 = relu(c2[j][0]), p01 = relu(c2[j][1]);
                float p10 = relu(c2[j][2]), p11 = relu(c2[j][3]);
                float2 a = *(const float2*)(hs0 + 8 * j);
                float2 b = *(const float2*)(hr0 + 8 * j);
                float2 e = *(const float2*)(hs1 + 8 * j);
                float2 d = *(const float2*)(hr1 + 8 * j);
                if (p00 != 0.f) atomicAdd(ag0 + 8 * j,     p00 * (b.x - a.x));
                if (p01 != 0.f) atomicAdd(ag0 + 8 * j + 1, p01 * (b.y - a.y));
                if (p10 != 0.f) atomicAdd(ag1 + 8 * j,     p10 * (d.x - e.x));
                if (p11 != 0.f) atomicAdd(ag1 + 8 * j + 1, p11 * (d.y - e.y));
            }
        }
    }
}

// ---------------------------------------------------------------------------
// out = h_d_prev + agg @ Wm
__global__ __launch_bounds__(256) void out_kernel(
    const float* __restrict__ h_d, const float* __restrict__ Wm,
    float* __restrict__ out)
{
    __shared__ float wm[4096];
    __shared__ float ag[64 * 68];
    int tid = threadIdx.x;
    for (int i = tid; i < 1024; i += 256)
        ((float4*)wm)[i] = ((const float4*)Wm)[i];
    int base = blockIdx.x * 64;
    for (int i = tid; i < 1024; i += 256) {
        int r = i >> 4, q = i & 15;
        int n = base + r;
        float4 v = make_float4(0.f, 0.f, 0.f, 0.f);
        if (n < NN) v = *((const float4*)(g_agg + (size_t)n * 64 + q * 4));
        *((float4*)(ag + r * 68 + q * 4)) = v;
    }
    __syncthreads();

    int row = tid >> 2;
    int cb = (tid & 3) * 16;
    float acc[16];
    #pragma unroll
    for (int j = 0; j < 16; j++) acc[j] = 0.f;
    #pragma unroll 8
    for (int k = 0; k < 64; k++) {
        float a = ag[row * 68 + k];
        float w[16];
        *(float4*)&w[0]  = *(float4*)(wm + k * 64 + cb);
        *(float4*)&w[4]  = *(float4*)(wm + k * 64 + cb + 4);
        *(float4*)&w[8]  = *(float4*)(wm + k * 64 + cb + 8);
        *(float4*)&w[12] = *(float4*)(wm + k * 64 + cb + 12);
        #pragma unroll
        for (int j = 0; j < 16; j++) acc[j] += a * w[j];
    }
    int n = base + row;
    if (n < NN) {
        #pragma unroll
        for (int v4 = 0; v4 < 4; v4++) {
            float4 h = *((const float4*)(h_d + (size_t)n * 64 + cb + v4 * 4));
            float4 o = make_float4(acc[v4 * 4 + 0] + h.x, acc[v4 * 4 + 1] + h.y,
                                   acc[v4 * 4 + 2] + h.z, acc[v4 * 4 + 3] + h.w);
            *((float4*)(out + (size_t)n * 64 + cb + v4 * 4)) = o;
        }
    }
}

// ---------------------------------------------------------------------------
#define NODE_SMEM ((32768 + 8448) * 4)   // 164864 B

extern "C" void kernel_launch(void* const* d_in, const int* in_sizes, int n_in,
                              void* d_out, int out_size) {
    const float* h_d_prev  = (const float*)d_in[0];
    const float* h_s       = (const float*)d_in[1];
    const float* edge_feat = (const float*)d_in[2];
    const int*   sender    = (const int*)d_in[3];
    const int*   receiver  = (const int*)d_in[4];
    const float* W0        = (const float*)d_in[5];
    const float* b0        = (const float*)d_in[6];
    const float* W1        = (const float*)d_in[7];
    const float* b1        = (const float*)d_in[8];
    const float* W2        = (const float*)d_in[9];
    const float* b2        = (const float*)d_in[10];
    const float* Wm        = (const float*)d_in[11];
    float* out = (float*)d_out;

    (void)cudaFuncSetAttribute(node_pre_kernel,
                               cudaFuncAttributeMaxDynamicSharedMemorySize, NODE_SMEM);
    (void)cudaFuncSetAttribute(edge_kernel,
                               cudaFuncAttributeMaxDynamicSharedMemorySize, EDGE_SMEM);

    zero_agg_kernel<<<(NN * 64 + 511) / 512, 512>>>();
    node_pre_kernel<<<(NN + 63) / 64, 512, NODE_SMEM>>>(h_s, h_d_prev, W0, b0);
    edge_kernel<<<148, 256, EDGE_SMEM>>>(edge_feat, sender, receiver, h_d_prev,
                                         W0, W1, b1, W2, b2);
    out_kernel<<<(NN + 63) / 64, 256>>>(h_d_prev, Wm, out);
}

// round 13
// speedup vs baseline: 1.2542x; 1.2542x over previous
#include <cuda_runtime.h>
#include <cuda_fp16.h>
#include <cstdint>

#define NN 50000
#define EE 800000
#define NWT 50000   // EE / 16 edges per warp-tile

// Scratch (device globals; no allocation allowed)
__device__ float g_preS[NN * 128];  // sender-side layer0 precompute (+b0)
__device__ float g_preR[NN * 128];  // receiver-side layer0 precompute
__device__ float g_agg[NN * 64];    // segment-sum accumulator

// ---------------------------------------------------------------------------
__device__ __forceinline__ float relu(float x) { return fmaxf(x, 0.f); }

// fp16 hi/residual split of a float pair -> packed half2 (low half = first)
__device__ __forceinline__ void split2h(float x, float y, uint32_t& hi, uint32_t& lo) {
    __half2 h = __floats2half2_rn(x, y);
    float2 hf = __half22float2(h);
    __half2 l = __floats2half2_rn(x - hf.x, y - hf.y);
    hi = *reinterpret_cast<uint32_t*>(&h);
    lo = *reinterpret_cast<uint32_t*>(&l);
}

__device__ __forceinline__ void mma_f16(float (&c)[4],
                                        uint32_t a0, uint32_t a1, uint32_t a2, uint32_t a3,
                                        uint32_t b0, uint32_t b1) {
    asm volatile(
        "mma.sync.aligned.m16n8k16.row.col.f32.f16.f16.f32 "
        "{%0,%1,%2,%3}, {%4,%5,%6,%7}, {%8,%9}, {%0,%1,%2,%3};"
        : "+f"(c[0]), "+f"(c[1]), "+f"(c[2]), "+f"(c[3])
        : "r"(a0), "r"(a1), "r"(a2), "r"(a3), "r"(b0), "r"(b1));
}

// Pack one B fragment (n8k16, col layout) as single fp16 for lane l of frag f.
__device__ __forceinline__ void pack_frag(const float* __restrict__ W, int ld,
                                          int k0, int n, uint2* dst, int idx) {
    float w00 = W[(size_t)k0 * ld + n];
    float w01 = W[(size_t)(k0 + 1) * ld + n];
    float w10 = W[(size_t)(k0 + 8) * ld + n];
    float w11 = W[(size_t)(k0 + 9) * ld + n];
    __half2 h0 = __floats2half2_rn(w00, w01);
    __half2 h1 = __floats2half2_rn(w10, w11);
    dst[idx] = make_uint2(*reinterpret_cast<uint32_t*>(&h0),
                          *reinterpret_cast<uint32_t*>(&h1));
}

// smem (uint2 units): W0F[2048] W1F[4096] W2F[2048]; then floats b1[128] b2[64]
#define EDGE_SMEM (8192 * 8 + 768)   // 66304 B

// ---------------------------------------------------------------------------
__global__ void zero_agg_kernel() {
    int i = blockIdx.x * blockDim.x + threadIdx.x;
    if (i < NN * 64) g_agg[i] = 0.0f;
}

// ---------------------------------------------------------------------------
// Per-node precompute (fp32): preS = h_s@W0[0:64] + h_d@W0[128:192] + b0
//                             preR = h_s@W0[64:128] + h_d@W0[192:256]
__global__ __launch_bounds__(512) void node_pre_kernel(
    const float* __restrict__ h_s, const float* __restrict__ h_d,
    const float* __restrict__ W0, const float* __restrict__ b0)
{
    extern __shared__ float sm[];
    float* ws = sm;
    float* nd = sm + 32768;

    int tid = threadIdx.x;
    for (int i = tid; i < 8192; i += 512)
        ((float4*)ws)[i] = ((const float4*)W0)[i];

    int base = blockIdx.x * 64;
    for (int i = tid; i < 2048; i += 512) {
        int r = i >> 5, q = i & 31;
        int n = base + r;
        float4 v = make_float4(0.f, 0.f, 0.f, 0.f);
        if (n < NN) {
            if (q < 16) v = ((const float4*)(h_s + (size_t)n * 64))[q];
            else        v = ((const float4*)(h_d + (size_t)n * 64))[q - 16];
        }
        *((float4*)(nd + r * 132 + q * 4)) = v;
    }
    __syncthreads();

    int ty = tid >> 4, tx = tid & 15;
    int c = tx * 8;
    int r0 = ty * 2;
    float accS[2][8], accR[2][8];
    #pragma unroll
    for (int i = 0; i < 2; i++)
        #pragma unroll
        for (int j = 0; j < 8; j++) { accS[i][j] = 0.f; accR[i][j] = 0.f; }

    #pragma unroll 4
    for (int k = 0; k < 64; k++) {
        float a0 = nd[r0 * 132 + k];
        float a1 = nd[r0 * 132 + 132 + k];
        float e0 = nd[r0 * 132 + 64 + k];
        float e1 = nd[r0 * 132 + 132 + 64 + k];
        float wsa[8], wra[8], wsb[8], wrb[8];
        *(float4*)&wsa[0] = *(float4*)(ws + k * 128 + c);
        *(float4*)&wsa[4] = *(float4*)(ws + k * 128 + c + 4);
        *(float4*)&wra[0] = *(float4*)(ws + (64 + k) * 128 + c);
        *(float4*)&wra[4] = *(float4*)(ws + (64 + k) * 128 + c + 4);
        *(float4*)&wsb[0] = *(float4*)(ws + (128 + k) * 128 + c);
        *(float4*)&wsb[4] = *(float4*)(ws + (128 + k) * 128 + c + 4);
        *(float4*)&wrb[0] = *(float4*)(ws + (192 + k) * 128 + c);
        *(float4*)&wrb[4] = *(float4*)(ws + (192 + k) * 128 + c + 4);
        #pragma unroll
        for (int j = 0; j < 8; j++) {
            accS[0][j] += a0 * wsa[j] + e0 * wsb[j];
            accS[1][j] += a1 * wsa[j] + e1 * wsb[j];
            accR[0][j] += a0 * wra[j] + e0 * wrb[j];
            accR[1][j] += a1 * wra[j] + e1 * wrb[j];
        }
    }

    float bv[8];
    *(float4*)&bv[0] = *(const float4*)(b0 + c);
    *(float4*)&bv[4] = *(const float4*)(b0 + c + 4);
    #pragma unroll
    for (int i = 0; i < 2; i++) {
        int n = base + r0 + i;
        if (n < NN) {
            #pragma unroll
            for (int j = 0; j < 8; j++) {
                g_preS[(size_t)n * 128 + c + j] = accS[i][j] + bv[j];
                g_preR[(size_t)n * 128 + c + j] = accR[i][j];
            }
        }
    }
}

// ---------------------------------------------------------------------------
// Warp-autonomous HMMA edge kernel: fp16 2-mma split (A hi+residual, W single).
__global__ __launch_bounds__(256, 1) void edge_kernel(
    const float* __restrict__ edge_feat,
    const int* __restrict__ sender, const int* __restrict__ receiver,
    const float* __restrict__ h_d,
    const float* __restrict__ W0, const float* __restrict__ W1,
    const float* __restrict__ b1, const float* __restrict__ W2,
    const float* __restrict__ b2)
{
    extern __shared__ unsigned char smraw[];
    uint2* W0F = (uint2*)smraw;        // 2048
    uint2* W1F = W0F + 2048;           // 4096
    uint2* W2F = W1F + 4096;           // 2048
    float* b1s = (float*)(W2F + 2048); // 128
    float* b2s = b1s + 128;            // 64

    int tid = threadIdx.x, wid = tid >> 5, lane = tid & 31;
    int q = lane & 3, g = lane >> 2;

    // ---- one-time fragment prepack (fp16 single) ----
    for (int i = tid; i < 2048; i += 256) {          // W0e: 64 frags
        int f = i >> 5, l = i & 31;
        int s = f >> 4, j = f & 15;
        pack_frag(W0 + 256 * 128, 128, 16 * s + (l & 3) * 2, 8 * j + (l >> 2), W0F, i);
    }
    for (int i = tid; i < 4096; i += 256) {          // W1: 128 frags
        int f = i >> 5, l = i & 31;
        int s = f >> 4, j = f & 15;
        pack_frag(W1, 128, 16 * s + (l & 3) * 2, 8 * j + (l >> 2), W1F, i);
    }
    for (int i = tid; i < 2048; i += 256) {          // W2: 64 frags
        int f = i >> 5, l = i & 31;
        int s = f >> 3, j = f & 7;
        pack_frag(W2, 64, 16 * s + (l & 3) * 2, 8 * j + (l >> 2), W2F, i);
    }
    if (tid < 128) b1s[tid] = b1[tid];
    if (tid < 64)  b2s[tid] = b2[tid];
    __syncthreads();

    for (int wt = blockIdx.x * 8 + wid; wt < NWT; wt += gridDim.x * 8) {
        int ebase = wt * 16;
        int r0 = ebase + g, r1 = r0 + 8;
        int s0 = sender[r0],   s1 = sender[r1];
        int rc0 = receiver[r0], rc1 = receiver[r1];

        // ---- layer 0 C init: preS[s] + preR[rc]  (b0 folded in preS) ----
        float c0[16][4];
        {
            const float* pS0 = g_preS + (size_t)s0 * 128 + 2 * q;
            const float* pS1 = g_preS + (size_t)s1 * 128 + 2 * q;
            const float* pR0 = g_preR + (size_t)rc0 * 128 + 2 * q;
            const float* pR1 = g_preR + (size_t)rc1 * 128 + 2 * q;
            #pragma unroll
            for (int j = 0; j < 16; j++) {
                float2 a = *(const float2*)(pS0 + 8 * j);
                float2 b = *(const float2*)(pR0 + 8 * j);
                float2 e = *(const float2*)(pS1 + 8 * j);
                float2 d = *(const float2*)(pR1 + 8 * j);
                c0[j][0] = a.x + b.x; c0[j][1] = a.y + b.y;
                c0[j][2] = e.x + d.x; c0[j][3] = e.y + d.y;
            }
        }

        // ---- layer 0 mma: C += ef[16,64] @ W0e[64,128] ----
        {
            const float* e0p = edge_feat + (size_t)r0 * 64 + 2 * q;
            const float* e1p = edge_feat + (size_t)r1 * 64 + 2 * q;
            #pragma unroll
            for (int s = 0; s < 4; s++) {
                float2 ea = *(const float2*)(e0p + 16 * s);
                float2 eb = *(const float2*)(e0p + 16 * s + 8);
                float2 ec = *(const float2*)(e1p + 16 * s);
                float2 ed = *(const float2*)(e1p + 16 * s + 8);
                uint32_t ah[4], al[4];
                split2h(ea.x, ea.y, ah[0], al[0]);
                split2h(ec.x, ec.y, ah[1], al[1]);
                split2h(eb.x, eb.y, ah[2], al[2]);
                split2h(ed.x, ed.y, ah[3], al[3]);
                #pragma unroll
                for (int j = 0; j < 16; j++) {
                    uint2 bf = W0F[(s * 16 + j) * 32 + lane];
                    mma_f16(c0[j], ah[0], ah[1], ah[2], ah[3], bf.x, bf.y);
                    mma_f16(c0[j], al[0], al[1], al[2], al[3], bf.x, bf.y);
                }
            }
        }

        // ---- layer 1: C1 = relu(C0) @ W1 + b1 ----
        float c1[16][4];
        #pragma unroll
        for (int j = 0; j < 16; j++) {
            float2 bb = *(const float2*)(b1s + 8 * j + 2 * q);
            c1[j][0] = bb.x; c1[j][1] = bb.y; c1[j][2] = bb.x; c1[j][3] = bb.y;
        }
        #pragma unroll
        for (int s = 0; s < 8; s++) {
            uint32_t ah[4], al[4];
            split2h(relu(c0[2 * s][0]),     relu(c0[2 * s][1]),     ah[0], al[0]);
            split2h(relu(c0[2 * s][2]),     relu(c0[2 * s][3]),     ah[1], al[1]);
            split2h(relu(c0[2 * s + 1][0]), relu(c0[2 * s + 1][1]), ah[2], al[2]);
            split2h(relu(c0[2 * s + 1][2]), relu(c0[2 * s + 1][3]), ah[3], al[3]);
            #pragma unroll
            for (int j = 0; j < 16; j++) {
                uint2 bf = W1F[(s * 16 + j) * 32 + lane];
                mma_f16(c1[j], ah[0], ah[1], ah[2], ah[3], bf.x, bf.y);
                mma_f16(c1[j], al[0], al[1], al[2], al[3], bf.x, bf.y);
            }
        }

        // ---- layer 2: C2 = relu(C1) @ W2 + b2 ----
        float c2[8][4];
        #pragma unroll
        for (int j = 0; j < 8; j++) {
            float2 bb = *(const float2*)(b2s + 8 * j + 2 * q);
            c2[j][0] = bb.x; c2[j][1] = bb.y; c2[j][2] = bb.x; c2[j][3] = bb.y;
        }
        #pragma unroll
        for (int s = 0; s < 8; s++) {
            uint32_t ah[4], al[4];
            split2h(relu(c1[2 * s][0]),     relu(c1[2 * s][1]),     ah[0], al[0]);
            split2h(relu(c1[2 * s][2]),     relu(c1[2 * s][3]),     ah[1], al[1]);
            split2h(relu(c1[2 * s + 1][0]), relu(c1[2 * s + 1][1]), ah[2], al[2]);
            split2h(relu(c1[2 * s + 1][2]), relu(c1[2 * s + 1][3]), ah[3], al[3]);
            #pragma unroll
            for (int j = 0; j < 8; j++) {
                uint2 bf = W2F[(s * 8 + j) * 32 + lane];
                mma_f16(c2[j], ah[0], ah[1], ah[2], ah[3], bf.x, bf.y);
                mma_f16(c2[j], al[0], al[1], al[2], al[3], bf.x, bf.y);
            }
        }

        // ---- epilogue: psi = relu(C2); scatter psi * (h_dj - h_di) ----
        {
            const float* hs0 = h_d + (size_t)s0 * 64 + 2 * q;
            const float* hr0 = h_d + (size_t)rc0 * 64 + 2 * q;
            const float* hs1 = h_d + (size_t)s1 * 64 + 2 * q;
            const float* hr1 = h_d + (size_t)rc1 * 64 + 2 * q;
            float* ag0 = g_agg + (size_t)rc0 * 64 + 2 * q;
            float* ag1 = g_agg + (size_t)rc1 * 64 + 2 * q;
            #pragma unroll
            for (int j = 0; j < 8; j++) {
                float p00 = relu(c2[j][0]), p01 = relu(c2[j][1]);
                float p10 = relu(c2[j][2]), p11 = relu(c2[j][3]);
                float2 a = *(const float2*)(hs0 + 8 * j);
                float2 b = *(const float2*)(hr0 + 8 * j);
                float2 e = *(const float2*)(hs1 + 8 * j);
                float2 d = *(const float2*)(hr1 + 8 * j);
                if (p00 != 0.f) atomicAdd(ag0 + 8 * j,     p00 * (b.x - a.x));
                if (p01 != 0.f) atomicAdd(ag0 + 8 * j + 1, p01 * (b.y - a.y));
                if (p10 != 0.f) atomicAdd(ag1 + 8 * j,     p10 * (d.x - e.x));
                if (p11 != 0.f) atomicAdd(ag1 + 8 * j + 1, p11 * (d.y - e.y));
            }
        }
    }
}

// ---------------------------------------------------------------------------
// out = h_d_prev + agg @ Wm
__global__ __launch_bounds__(256) void out_kernel(
    const float* __restrict__ h_d, const float* __restrict__ Wm,
    float* __restrict__ out)
{
    __shared__ float wm[4096];
    __shared__ float ag[64 * 68];
    int tid = threadIdx.x;
    for (int i = tid; i < 1024; i += 256)
        ((float4*)wm)[i] = ((const float4*)Wm)[i];
    int base = blockIdx.x * 64;
    for (int i = tid; i < 1024; i += 256) {
        int r = i >> 4, q = i & 15;
        int n = base + r;
        float4 v = make_float4(0.f, 0.f, 0.f, 0.f);
        if (n < NN) v = *((const float4*)(g_agg + (size_t)n * 64 + q * 4));
        *((float4*)(ag + r * 68 + q * 4)) = v;
    }
    __syncthreads();

    int row = tid >> 2;
    int cb = (tid & 3) * 16;
    float acc[16];
    #pragma unroll
    for (int j = 0; j < 16; j++) acc[j] = 0.f;
    #pragma unroll 8
    for (int k = 0; k < 64; k++) {
        float a = ag[row * 68 + k];
        float w[16];
        *(float4*)&w[0]  = *(float4*)(wm + k * 64 + cb);
        *(float4*)&w[4]  = *(float4*)(wm + k * 64 + cb + 4);
        *(float4*)&w[8]  = *(float4*)(wm + k * 64 + cb + 8);
        *(float4*)&w[12] = *(float4*)(wm + k * 64 + cb + 12);
        #pragma unroll
        for (int j = 0; j < 16; j++) acc[j] += a * w[j];
    }
    int n = base + row;
    if (n < NN) {
        #pragma unroll
        for (int v4 = 0; v4 < 4; v4++) {
            float4 h = *((const float4*)(h_d + (size_t)n * 64 + cb + v4 * 4));
            float4 o = make_float4(acc[v4 * 4 + 0] + h.x, acc[v4 * 4 + 1] + h.y,
                                   acc[v4 * 4 + 2] + h.z, acc[v4 * 4 + 3] + h.w);
            *((float4*)(out + (size_t)n * 64 + cb + v4 * 4)) = o;
        }
    }
}

// ---------------------------------------------------------------------------
#define NODE_SMEM ((32768 + 8448) * 4)   // 164864 B

extern "C" void kernel_launch(void* const* d_in, const int* in_sizes, int n_in,
                              void* d_out, int out_size) {
    const float* h_d_prev  = (const float*)d_in[0];
    const float* h_s       = (const float*)d_in[1];
    const float* edge_feat = (const float*)d_in[2];
    const int*   sender    = (const int*)d_in[3];
    const int*   receiver  = (const int*)d_in[4];
    const float* W0        = (const float*)d_in[5];
    const float* b0        = (const float*)d_in[6];
    const float* W1        = (const float*)d_in[7];
    const float* b1        = (const float*)d_in[8];
    const float* W2        = (const float*)d_in[9];
    const float* b2        = (const float*)d_in[10];
    const float* Wm        = (const float*)d_in[11];
    float* out = (float*)d_out;

    (void)cudaFuncSetAttribute(node_pre_kernel,
                               cudaFuncAttributeMaxDynamicSharedMemorySize, NODE_SMEM);
    (void)cudaFuncSetAttribute(edge_kernel,
                               cudaFuncAttributeMaxDynamicSharedMemorySize, EDGE_SMEM);

    zero_agg_kernel<<<(NN * 64 + 511) / 512, 512>>>();
    node_pre_kernel<<<(NN + 63) / 64, 512, NODE_SMEM>>>(h_s, h_d_prev, W0, b0);
    edge_kernel<<<148, 256, EDGE_SMEM>>>(edge_feat, sender, receiver, h_d_prev,
                                         W0, W1, b1, W2, b2);
    out_kernel<<<(NN + 63) / 64, 256>>>(h_d_prev, Wm, out);
}

// round 17
// speedup vs baseline: 1.3426x; 1.0705x over previous
#include <cuda_runtime.h>
#include <cuda_fp16.h>
#include <cstdint>

#define NN 50000
#define EE 800000
#define NWT 50000   // EE / 16 edges per warp-tile

// Scratch (device globals; no allocation allowed)
__device__ float g_preS[NN * 128];  // sender-side layer0 precompute (+b0)
__device__ float g_preR[NN * 128];  // receiver-side layer0 precompute
__device__ float g_agg[NN * 64];    // segment-sum accumulator

// ---------------------------------------------------------------------------
__device__ __forceinline__ float relu(float x) { return fmaxf(x, 0.f); }

// pack float pair -> fp16x2 (single rounding, no residual)
__device__ __forceinline__ uint32_t cvt2h(float x, float y) {
    __half2 h = __floats2half2_rn(x, y);
    return *reinterpret_cast<uint32_t*>(&h);
}

__device__ __forceinline__ void mma_f16(float (&c)[4],
                                        uint32_t a0, uint32_t a1, uint32_t a2, uint32_t a3,
                                        uint32_t b0, uint32_t b1) {
    asm volatile(
        "mma.sync.aligned.m16n8k16.row.col.f32.f16.f16.f32 "
        "{%0,%1,%2,%3}, {%4,%5,%6,%7}, {%8,%9}, {%0,%1,%2,%3};"
        : "+f"(c[0]), "+f"(c[1]), "+f"(c[2]), "+f"(c[3])
        : "r"(a0), "r"(a1), "r"(a2), "r"(a3), "r"(b0), "r"(b1));
}

// Pack one B fragment (n8k16, col layout) as single fp16 for lane l of frag f.
__device__ __forceinline__ void pack_frag(const float* __restrict__ W, int ld,
                                          int k0, int n, uint2* dst, int idx) {
    float w00 = W[(size_t)k0 * ld + n];
    float w01 = W[(size_t)(k0 + 1) * ld + n];
    float w10 = W[(size_t)(k0 + 8) * ld + n];
    float w11 = W[(size_t)(k0 + 9) * ld + n];
    dst[idx] = make_uint2(cvt2h(w00, w01), cvt2h(w10, w11));
}

// smem (uint2 units): W0F[2048] W1F[4096] W2F[2048]; then floats b1[128] b2[64]
#define EDGE_SMEM (8192 * 8 + 768)   // 66304 B

// ---------------------------------------------------------------------------
__global__ void zero_agg_kernel() {
    int i = blockIdx.x * blockDim.x + threadIdx.x;
    if (i < NN * 64) g_agg[i] = 0.0f;
}

// ---------------------------------------------------------------------------
// Per-node precompute (fp32): preS = h_s@W0[0:64] + h_d@W0[128:192] + b0
//                             preR = h_s@W0[64:128] + h_d@W0[192:256]
__global__ __launch_bounds__(512) void node_pre_kernel(
    const float* __restrict__ h_s, const float* __restrict__ h_d,
    const float* __restrict__ W0, const float* __restrict__ b0)
{
    extern __shared__ float sm[];
    float* ws = sm;
    float* nd = sm + 32768;

    int tid = threadIdx.x;
    for (int i = tid; i < 8192; i += 512)
        ((float4*)ws)[i] = ((const float4*)W0)[i];

    int base = blockIdx.x * 64;
    for (int i = tid; i < 2048; i += 512) {
        int r = i >> 5, q = i & 31;
        int n = base + r;
        float4 v = make_float4(0.f, 0.f, 0.f, 0.f);
        if (n < NN) {
            if (q < 16) v = ((const float4*)(h_s + (size_t)n * 64))[q];
            else        v = ((const float4*)(h_d + (size_t)n * 64))[q - 16];
        }
        *((float4*)(nd + r * 132 + q * 4)) = v;
    }
    __syncthreads();

    int ty = tid >> 4, tx = tid & 15;
    int c = tx * 8;
    int r0 = ty * 2;
    float accS[2][8], accR[2][8];
    #pragma unroll
    for (int i = 0; i < 2; i++)
        #pragma unroll
        for (int j = 0; j < 8; j++) { accS[i][j] = 0.f; accR[i][j] = 0.f; }

    #pragma unroll 4
    for (int k = 0; k < 64; k++) {
        float a0 = nd[r0 * 132 + k];
        float a1 = nd[r0 * 132 + 132 + k];
        float e0 = nd[r0 * 132 + 64 + k];
        float e1 = nd[r0 * 132 + 132 + 64 + k];
        float wsa[8], wra[8], wsb[8], wrb[8];
        *(float4*)&wsa[0] = *(float4*)(ws + k * 128 + c);
        *(float4*)&wsa[4] = *(float4*)(ws + k * 128 + c + 4);
        *(float4*)&wra[0] = *(float4*)(ws + (64 + k) * 128 + c);
        *(float4*)&wra[4] = *(float4*)(ws + (64 + k) * 128 + c + 4);
        *(float4*)&wsb[0] = *(float4*)(ws + (128 + k) * 128 + c);
        *(float4*)&wsb[4] = *(float4*)(ws + (128 + k) * 128 + c + 4);
        *(float4*)&wrb[0] = *(float4*)(ws + (192 + k) * 128 + c);
        *(float4*)&wrb[4] = *(float4*)(ws + (192 + k) * 128 + c + 4);
        #pragma unroll
        for (int j = 0; j < 8; j++) {
            accS[0][j] += a0 * wsa[j] + e0 * wsb[j];
            accS[1][j] += a1 * wsa[j] + e1 * wsb[j];
            accR[0][j] += a0 * wra[j] + e0 * wrb[j];
            accR[1][j] += a1 * wra[j] + e1 * wrb[j];
        }
    }

    float bv[8];
    *(float4*)&bv[0] = *(const float4*)(b0 + c);
    *(float4*)&bv[4] = *(const float4*)(b0 + c + 4);
    #pragma unroll
    for (int i = 0; i < 2; i++) {
        int n = base + r0 + i;
        if (n < NN) {
            #pragma unroll
            for (int j = 0; j < 8; j++) {
                g_preS[(size_t)n * 128 + c + j] = accS[i][j] + bv[j];
                g_preR[(size_t)n * 128 + c + j] = accR[i][j];
            }
        }
    }
}

// ---------------------------------------------------------------------------
// Warp-autonomous HMMA edge kernel: single fp16 mma per fragment.
__global__ __launch_bounds__(256, 1) void edge_kernel(
    const float* __restrict__ edge_feat,
    const int* __restrict__ sender, const int* __restrict__ receiver,
    const float* __restrict__ h_d,
    const float* __restrict__ W0, const float* __restrict__ W1,
    const float* __restrict__ b1, const float* __restrict__ W2,
    const float* __restrict__ b2)
{
    extern __shared__ unsigned char smraw[];
    uint2* W0F = (uint2*)smraw;        // 2048
    uint2* W1F = W0F + 2048;           // 4096
    uint2* W2F = W1F + 4096;           // 2048
    float* b1s = (float*)(W2F + 2048); // 128
    float* b2s = b1s + 128;            // 64

    int tid = threadIdx.x, wid = tid >> 5, lane = tid & 31;
    int q = lane & 3, g = lane >> 2;

    // ---- one-time fragment prepack (fp16 single) ----
    for (int i = tid; i < 2048; i += 256) {          // W0e: 64 frags
        int f = i >> 5, l = i & 31;
        int s = f >> 4, j = f & 15;
        pack_frag(W0 + 256 * 128, 128, 16 * s + (l & 3) * 2, 8 * j + (l >> 2), W0F, i);
    }
    for (int i = tid; i < 4096; i += 256) {          // W1: 128 frags
        int f = i >> 5, l = i & 31;
        int s = f >> 4, j = f & 15;
        pack_frag(W1, 128, 16 * s + (l & 3) * 2, 8 * j + (l >> 2), W1F, i);
    }
    for (int i = tid; i < 2048; i += 256) {          // W2: 64 frags
        int f = i >> 5, l = i & 31;
        int s = f >> 3, j = f & 7;
        pack_frag(W2, 64, 16 * s + (l & 3) * 2, 8 * j + (l >> 2), W2F, i);
    }
    if (tid < 128) b1s[tid] = b1[tid];
    if (tid < 64)  b2s[tid] = b2[tid];
    __syncthreads();

    for (int wt = blockIdx.x * 8 + wid; wt < NWT; wt += gridDim.x * 8) {
        int ebase = wt * 16;
        int r0 = ebase + g, r1 = r0 + 8;
        int s0 = sender[r0],   s1 = sender[r1];
        int rc0 = receiver[r0], rc1 = receiver[r1];

        // ---- layer 0 C init: preS[s] + preR[rc]  (b0 folded in preS) ----
        float c0[16][4];
        {
            const float* pS0 = g_preS + (size_t)s0 * 128 + 2 * q;
            const float* pS1 = g_preS + (size_t)s1 * 128 + 2 * q;
            const float* pR0 = g_preR + (size_t)rc0 * 128 + 2 * q;
            const float* pR1 = g_preR + (size_t)rc1 * 128 + 2 * q;
            #pragma unroll
            for (int j = 0; j < 16; j++) {
                float2 a = *(const float2*)(pS0 + 8 * j);
                float2 b = *(const float2*)(pR0 + 8 * j);
                float2 e = *(const float2*)(pS1 + 8 * j);
                float2 d = *(const float2*)(pR1 + 8 * j);
                c0[j][0] = a.x + b.x; c0[j][1] = a.y + b.y;
                c0[j][2] = e.x + d.x; c0[j][3] = e.y + d.y;
            }
        }

        // ---- layer 0 mma: C += ef[16,64] @ W0e[64,128] ----
        {
            const float* e0p = edge_feat + (size_t)r0 * 64 + 2 * q;
            const float* e1p = edge_feat + (size_t)r1 * 64 + 2 * q;
            #pragma unroll
            for (int s = 0; s < 4; s++) {
                float2 ea = *(const float2*)(e0p + 16 * s);
                float2 eb = *(const float2*)(e0p + 16 * s + 8);
                float2 ec = *(const float2*)(e1p + 16 * s);
                float2 ed = *(const float2*)(e1p + 16 * s + 8);
                uint32_t ah[4];
                ah[0] = cvt2h(ea.x, ea.y);
                ah[1] = cvt2h(ec.x, ec.y);
                ah[2] = cvt2h(eb.x, eb.y);
                ah[3] = cvt2h(ed.x, ed.y);
                #pragma unroll
                for (int j = 0; j < 16; j++) {
                    uint2 bf = W0F[(s * 16 + j) * 32 + lane];
                    mma_f16(c0[j], ah[0], ah[1], ah[2], ah[3], bf.x, bf.y);
                }
            }
        }

        // ---- layer 1: C1 = relu(C0) @ W1 + b1 ----
        float c1[16][4];
        #pragma unroll
        for (int j = 0; j < 16; j++) {
            float2 bb = *(const float2*)(b1s + 8 * j + 2 * q);
            c1[j][0] = bb.x; c1[j][1] = bb.y; c1[j][2] = bb.x; c1[j][3] = bb.y;
        }
        #pragma unroll
        for (int s = 0; s < 8; s++) {
            uint32_t ah[4];
            ah[0] = cvt2h(relu(c0[2 * s][0]),     relu(c0[2 * s][1]));
            ah[1] = cvt2h(relu(c0[2 * s][2]),     relu(c0[2 * s][3]));
            ah[2] = cvt2h(relu(c0[2 * s + 1][0]), relu(c0[2 * s + 1][1]));
            ah[3] = cvt2h(relu(c0[2 * s + 1][2]), relu(c0[2 * s + 1][3]));
            #pragma unroll
            for (int j = 0; j < 16; j++) {
                uint2 bf = W1F[(s * 16 + j) * 32 + lane];
                mma_f16(c1[j], ah[0], ah[1], ah[2], ah[3], bf.x, bf.y);
            }
        }

        // ---- layer 2: C2 = relu(C1) @ W2 + b2 ----
        float c2[8][4];
        #pragma unroll
        for (int j = 0; j < 8; j++) {
            float2 bb = *(const float2*)(b2s + 8 * j + 2 * q);
            c2[j][0] = bb.x; c2[j][1] = bb.y; c2[j][2] = bb.x; c2[j][3] = bb.y;
        }
        #pragma unroll
        for (int s = 0; s < 8; s++) {
            uint32_t ah[4];
            ah[0] = cvt2h(relu(c1[2 * s][0]),     relu(c1[2 * s][1]));
            ah[1] = cvt2h(relu(c1[2 * s][2]),     relu(c1[2 * s][3]));
            ah[2] = cvt2h(relu(c1[2 * s + 1][0]), relu(c1[2 * s + 1][1]));
            ah[3] = cvt2h(relu(c1[2 * s + 1][2]), relu(c1[2 * s + 1][3]));
            #pragma unroll
            for (int j = 0; j < 8; j++) {
                uint2 bf = W2F[(s * 8 + j) * 32 + lane];
                mma_f16(c2[j], ah[0], ah[1], ah[2], ah[3], bf.x, bf.y);
            }
        }

        // ---- epilogue: psi = relu(C2); scatter psi * (h_dj - h_di) ----
        {
            const float* hs0 = h_d + (size_t)s0 * 64 + 2 * q;
            const float* hr0 = h_d + (size_t)rc0 * 64 + 2 * q;
            const float* hs1 = h_d + (size_t)s1 * 64 + 2 * q;
            const float* hr1 = h_d + (size_t)rc1 * 64 + 2 * q;
            float* ag0 = g_agg + (size_t)rc0 * 64 + 2 * q;
            float* ag1 = g_agg + (size_t)rc1 * 64 + 2 * q;
            #pragma unroll
            for (int j = 0; j < 8; j++) {
                float p00 = relu(c2[j][0]), p01 = relu(c2[j][1]);
                float p10 = relu(c2[j][2]), p11 = relu(c2[j][3]);
                float2 a = *(const float2*)(hs0 + 8 * j);
                float2 b = *(const float2*)(hr0 + 8 * j);
                float2 e = *(const float2*)(hs1 + 8 * j);
                float2 d = *(const float2*)(hr1 + 8 * j);
                if (p00 != 0.f) atomicAdd(ag0 + 8 * j,     p00 * (b.x - a.x));
                if (p01 != 0.f) atomicAdd(ag0 + 8 * j + 1, p01 * (b.y - a.y));
                if (p10 != 0.f) atomicAdd(ag1 + 8 * j,     p10 * (d.x - e.x));
                if (p11 != 0.f) atomicAdd(ag1 + 8 * j + 1, p11 * (d.y - e.y));
            }
        }
    }
}

// ---------------------------------------------------------------------------
// out = h_d_prev + agg @ Wm
__global__ __launch_bounds__(256) void out_kernel(
    const float* __restrict__ h_d, const float* __restrict__ Wm,
    float* __restrict__ out)
{
    __shared__ float wm[4096];
    __shared__ float ag[64 * 68];
    int tid = threadIdx.x;
    for (int i = tid; i < 1024; i += 256)
        ((float4*)wm)[i] = ((const float4*)Wm)[i];
    int base = blockIdx.x * 64;
    for (int i = tid; i < 1024; i += 256) {
        int r = i >> 4, q = i & 15;
        int n = base + r;
        float4 v = make_float4(0.f, 0.f, 0.f, 0.f);
        if (n < NN) v = *((const float4*)(g_agg + (size_t)n * 64 + q * 4));
        *((float4*)(ag + r * 68 + q * 4)) = v;
    }
    __syncthreads();

    int row = tid >> 2;
    int cb = (tid & 3) * 16;
    float acc[16];
    #pragma unroll
    for (int j = 0; j < 16; j++) acc[j] = 0.f;
    #pragma unroll 8
    for (int k = 0; k < 64; k++) {
        float a = ag[row * 68 + k];
        float w[16];
        *(float4*)&w[0]  = *(float4*)(wm + k * 64 + cb);
        *(float4*)&w[4]  = *(float4*)(wm + k * 64 + cb + 4);
        *(float4*)&w[8]  = *(float4*)(wm + k * 64 + cb + 8);
        *(float4*)&w[12] = *(float4*)(wm + k * 64 + cb + 12);
        #pragma unroll
        for (int j = 0; j < 16; j++) acc[j] += a * w[j];
    }
    int n = base + row;
    if (n < NN) {
        #pragma unroll
        for (int v4 = 0; v4 < 4; v4++) {
            float4 h = *((const float4*)(h_d + (size_t)n * 64 + cb + v4 * 4));
            float4 o = make_float4(acc[v4 * 4 + 0] + h.x, acc[v4 * 4 + 1] + h.y,
                                   acc[v4 * 4 + 2] + h.z, acc[v4 * 4 + 3] + h.w);
            *((float4*)(out + (size_t)n * 64 + cb + v4 * 4)) = o;
        }
    }
}

// ---------------------------------------------------------------------------
#define NODE_SMEM ((32768 + 8448) * 4)   // 164864 B

extern "C" void kernel_launch(void* const* d_in, const int* in_sizes, int n_in,
                              void* d_out, int out_size) {
    const float* h_d_prev  = (const float*)d_in[0];
    const float* h_s       = (const float*)d_in[1];
    const float* edge_feat = (const float*)d_in[2];
    const int*   sender    = (const int*)d_in[3];
    const int*   receiver  = (const int*)d_in[4];
    const float* W0        = (const float*)d_in[5];
    const float* b0        = (const float*)d_in[6];
    const float* W1        = (const float*)d_in[7];
    const float* b1        = (const float*)d_in[8];
    const float* W2        = (const float*)d_in[9];
    const float* b2        = (const float*)d_in[10];
    const float* Wm        = (const float*)d_in[11];
    float* out = (float*)d_out;

    (void)cudaFuncSetAttribute(node_pre_kernel,
                               cudaFuncAttributeMaxDynamicSharedMemorySize, NODE_SMEM);
    (void)cudaFuncSetAttribute(edge_kernel,
                               cudaFuncAttributeMaxDynamicSharedMemorySize, EDGE_SMEM);

    zero_agg_kernel<<<(NN * 64 + 511) / 512, 512>>>();
    node_pre_kernel<<<(NN + 63) / 64, 512, NODE_SMEM>>>(h_s, h_d_prev, W0, b0);
    edge_kernel<<<148, 256, EDGE_SMEM>>>(edge_feat, sender, receiver, h_d_prev,
                                         W0, W1, b1, W2, b2);
    out_kernel<<<(NN + 63) / 64, 256>>>(h_d_prev, Wm, out);
}